// round 14
// baseline (speedup 1.0000x reference)
#include <cuda_runtime.h>
#include <math.h>

#define NATOMS 4096
#define KX 14
#define KY 15
#define KZ 16
#define NGRID (KX*KY*KZ)          /* 3360 */
#define KYZ (KY*KZ)               /* 240 */
#define ALPHAF 4.985823141035867f
#define ALPHAD 4.985823141035867
#define COULOMB 138.935
#define CUT2 0.25f
#define NBLK 148                  /* one block per SM: all resident */
#define NTHR 1024
#define NMESH 14                  /* mesh pipeline blocks (one per gx plane) */
#define NDIRB (NBLK - NMESH)      /* 134 direct blocks */
#define TDIM 32                   /* 32x32 triangle of 128-atom tiles */
#define TILES 528                 /* 32*33/2 */
#define TSIZE 128

// -------- device scratch (static, allocation-free) --------
__device__ float  g_grid[NGRID];
__device__ float2 g_cy[NGRID];
__device__ double g_edir, g_erec, g_q2;
__device__ double g_V;
__device__ unsigned int g_done;        // zero-init; reset by combiner each run
__device__ unsigned int g_mcount;      // mesh barrier counter
__device__ unsigned int g_mgen;        // mesh barrier generation (monotonic)

// -------- mesh-subset barrier (NMESH blocks, all resident) --------
__device__ __forceinline__ void meshbar() {
    __syncthreads();
    if (threadIdx.x == 0) {
        __threadfence();
        unsigned gen = *(volatile unsigned*)&g_mgen;
        if (atomicAdd(&g_mcount, 1u) == NMESH - 1) {
            *(volatile unsigned*)&g_mcount = 0;
            __threadfence();
            *(volatile unsigned*)&g_mgen = gen + 1;
        } else {
            while (*(volatile unsigned*)&g_mgen == gen) __nanosleep(32);
        }
        __threadfence();
    }
    __syncthreads();
}

// -------- fast erfc (Abramowitz-Stegun 7.1.26, abs err <= 1.5e-7) --------
__device__ __forceinline__ float erfc_fast(float x) {
    float t = __fdividef(1.0f, fmaf(0.3275911f, x, 1.0f));
    float p = fmaf(fmaf(fmaf(fmaf(1.061405429f, t, -1.453152027f),
                             t, 1.421413741f),
                        t, -0.284496736f),
                   t, 0.254829592f) * t;
    return p * __expf(-x * x);
}

// -------- order-5 cardinal B-spline: d[k] = M5(w+k), w in [0,1) --------
__device__ __forceinline__ void bspline5(float w, float d[5]) {
    float b2_0 = w, b2_1 = 1.0f - w;
    float b3_0 = 0.5f * w * b2_0;
    float b3_1 = 0.5f * ((w + 1.0f) * b2_1 + (2.0f - w) * b2_0);
    float b3_2 = 0.5f * (1.0f - w) * b2_1;
    const float i3 = 1.0f / 3.0f;
    float b4_0 = i3 * w * b3_0;
    float b4_1 = i3 * ((w + 1.0f) * b3_1 + (3.0f - w) * b3_0);
    float b4_2 = i3 * ((w + 2.0f) * b3_2 + (2.0f - w) * b3_1);
    float b4_3 = i3 * (1.0f - w) * b3_2;
    d[0] = 0.25f * w * b4_0;
    d[1] = 0.25f * ((w + 1.0f) * b4_1 + (4.0f - w) * b4_0);
    d[2] = 0.25f * ((w + 2.0f) * b4_2 + (3.0f - w) * b4_1);
    d[3] = 0.25f * ((w + 3.0f) * b4_3 + (2.0f - w) * b4_2);
    d[4] = 0.25f * (1.0f - w) * b4_3;
}

__global__ void __launch_bounds__(NTHR) k_all(const float* __restrict__ pos,
                                              const float* __restrict__ chg,
                                              const float* __restrict__ box,
                                              float* __restrict__ out) {
    __shared__ float  s_twc[45], s_tws[45], s_bmod[45];
    __shared__ float  s_inv[9];
    __shared__ float  s_plane[240];
    __shared__ float  s_czr[240], s_czi[240];
    __shared__ float4 sj[TSIZE];
    __shared__ float  sred[32];

    const int gid = blockIdx.x;
    const int tid = threadIdx.x;
    const int lane = tid & 31;
    const int wid = tid >> 5;

    if (gid < NMESH) {
        // ================= MESH PIPELINE (blocks 0..13) =================
        const int m = gid;   // gx plane owned by this block

        // ---- local tables ----
        if (tid < 45) {
            int K, mm;
            if      (tid < KX)      { K = KX; mm = tid; }
            else if (tid < KX + KY) { K = KY; mm = tid - KX; }
            else                    { K = KZ; mm = tid - KX - KY; }
            float s, c;
            sincospif(2.0f * (float)mm / (float)K, &s, &c);
            s_twc[tid] = c; s_tws[tid] = s;
            const float Mv[4] = {1.0f/24.0f, 11.0f/24.0f, 11.0f/24.0f, 1.0f/24.0f};
            float dr = 0.0f, di = 0.0f;
            #pragma unroll
            for (int k = 0; k < 4; k++) {
                int p = (mm * k) % K;
                float ss, cc;
                sincospif(2.0f * (float)p / (float)K, &ss, &cc);
                dr += Mv[k] * cc; di += Mv[k] * ss;
            }
            float d2 = dr*dr + di*di;
            s_bmod[tid] = (d2 < 1e-7f) ? 0.0f : 1.0f / d2;
        }
        if (tid == 64) {   // separate warp from table warp
            double b00 = box[0], b01 = box[1], b02 = box[2];
            double b10 = box[3], b11 = box[4], b12 = box[5];
            double b20 = box[6], b21 = box[7], b22 = box[8];
            double c00 =  (b11*b22 - b12*b21);
            double c01 = -(b10*b22 - b12*b20);
            double c02 =  (b10*b21 - b11*b20);
            double det = b00*c00 + b01*c01 + b02*c02;
            double id = 1.0 / det;
            s_inv[0] = (float)(c00 * id);
            s_inv[1] = (float)(-(b01*b22 - b02*b21) * id);
            s_inv[2] = (float)( (b01*b12 - b02*b11) * id);
            s_inv[3] = (float)(c01 * id);
            s_inv[4] = (float)( (b00*b22 - b02*b20) * id);
            s_inv[5] = (float)(-(b00*b12 - b02*b10) * id);
            s_inv[6] = (float)(c02 * id);
            s_inv[7] = (float)(-(b00*b21 - b01*b20) * id);
            s_inv[8] = (float)( (b00*b11 - b01*b10) * id);
            if (m == 0) g_V = fabs(det);
        }
        // ---- zero own plane ----
        if (tid < KYZ) g_grid[m * KYZ + tid] = 0.0f;
        meshbar();   // grid zeroed, tables local

        // ---- spread: items (atom-in-class x x-slice) + q^2 ----
        {
            float q2c = 0.0f;
            for (int idx = tid; idx < 293 * 5; idx += NTHR) {
                int k  = idx / 5;
                int aa = idx - 5 * k;
                int a  = m + NMESH * k;
                if (a >= NATOMS) break;
                float q = chg[a];
                if (aa == 0) q2c += q * q;
                float px = pos[3*a], py = pos[3*a+1], pz = pos[3*a+2];
                const int Ks[3] = {KX, KY, KZ};
                float wts[3][5];
                int   idxg[3][5];
                #pragma unroll
                for (int d = 0; d < 3; d++) {
                    float f = px*s_inv[0+d] + py*s_inv[3+d] + pz*s_inv[6+d];
                    f -= floorf(f);
                    if (f >= 1.0f) f = 0.0f;
                    float u  = f * (float)Ks[d];
                    float fl = floorf(u);
                    int base = (int)fl;
                    if (base >= Ks[d]) { base = Ks[d] - 1; fl = (float)base; }
                    float w = u - fl;
                    bspline5(w, wts[d]);
                    #pragma unroll
                    for (int kk = 0; kk < 5; kk++) {
                        int ii = base - kk;
                        if (ii < 0) ii += Ks[d];
                        idxg[d][kk] = ii;
                    }
                }
                int offx = idxg[0][aa] * KYZ;
                float wx = q * wts[0][aa];
                #pragma unroll
                for (int bb = 0; bb < 5; bb++) {
                    float wab = wx * wts[1][bb];
                    int off = offx + idxg[1][bb] * KZ;
                    #pragma unroll
                    for (int cc = 0; cc < 5; cc++)
                        atomicAdd(&g_grid[off + idxg[2][cc]], wab * wts[2][cc]);
                }
            }
            #pragma unroll
            for (int o = 16; o; o >>= 1) q2c += __shfl_xor_sync(0xffffffffu, q2c, o);
            if (lane == 0) sred[wid] = q2c;
            __syncthreads();
            if (tid == 0) {
                float s = 0.0f;
                #pragma unroll
                for (int w = 0; w < 32; w++) s += sred[w];
                if (s != 0.0f) atomicAdd(&g_q2, (double)s);
            }
        }
        meshbar();   // full mesh ready

        // ---- z-DFT + y-DFT of own plane, in smem ----
        if (tid < KYZ) s_plane[tid] = g_grid[m * KYZ + tid];
        __syncthreads();
        if (tid < KYZ) {               // out (gy, mz)
            int gy = tid >> 4, mz = tid & 15;
            float fr = 0.0f, fi = 0.0f;
            #pragma unroll
            for (int gz = 0; gz < KZ; gz++) {
                int p = (mz * gz) & (KZ - 1);
                float v = s_plane[(gy << 4) + gz];
                fr = fmaf(v,  s_twc[29 + p], fr);
                fi = fmaf(v, -s_tws[29 + p], fi);
            }
            s_czr[tid] = fr; s_czi[tid] = fi;
        }
        __syncthreads();
        if (tid < KYZ) {               // out (my, mz)
            int my = tid >> 4, mz = tid & 15;
            float fr = 0.0f, fi = 0.0f;
            #pragma unroll
            for (int gy = 0; gy < KY; gy++) {
                float ar = s_czr[(gy << 4) + mz], ai = s_czi[(gy << 4) + mz];
                int p = (my * gy) % KY;
                float c = s_twc[14 + p], s = s_tws[14 + p];
                fr += ar * c + ai * s;
                fi += ai * c - ar * s;
            }
            g_cy[m * KYZ + tid] = make_float2(fr, fi);
        }
        meshbar();   // all planes' cy ready

        // ---- x-DFT for mx = m + green/B reduce ----
        {
            float contrib = 0.0f;
            if (tid < KYZ) {
                int mx = m, my = tid >> 4, mz = tid & 15;
                float fr = 0.0f, fi = 0.0f;
                #pragma unroll
                for (int gx = 0; gx < KX; gx++) {
                    float2 cv = g_cy[gx * KYZ + tid];
                    int p = (mx * gx) % KX;
                    float c = s_twc[p], s = s_tws[p];
                    fr += cv.x * c + cv.y * s;
                    fi += cv.y * c - cv.x * s;
                }
                int smx = (mx <= (KX - 1) / 2) ? mx : mx - KX;
                int smy = (my <= (KY - 1) / 2) ? my : my - KY;
                int smz = (mz <= (KZ - 1) / 2) ? mz : mz - KZ;
                float fx = (float)smx, fy = (float)smy, fz = (float)smz;
                float mv0 = fx*s_inv[0] + fy*s_inv[1] + fz*s_inv[2];
                float mv1 = fx*s_inv[3] + fy*s_inv[4] + fz*s_inv[5];
                float mv2 = fx*s_inv[6] + fy*s_inv[7] + fz*s_inv[8];
                float m2 = mv0*mv0 + mv1*mv1 + mv2*mv2;
                if (m2 > 0.0f) {
                    const float pi2_over_a2 = (float)(9.869604401089358 / (ALPHAD * ALPHAD));
                    float green = __expf(-pi2_over_a2 * m2) / m2;
                    float B = s_bmod[mx] * s_bmod[14 + my] * s_bmod[29 + mz];
                    contrib = green * B * (fr*fr + fi*fi);
                }
            }
            #pragma unroll
            for (int o = 16; o; o >>= 1) contrib += __shfl_xor_sync(0xffffffffu, contrib, o);
            if (lane == 0) sred[wid] = contrib;
            __syncthreads();
            if (tid == 0) {
                float s = 0.0f;
                #pragma unroll
                for (int w = 0; w < 32; w++) s += sred[w];
                if (s != 0.0f) atomicAdd(&g_erec, (double)s);
            }
        }
    } else {
        // ================= DIRECT BLOCKS (14..147): no barriers =================
        float Lx = box[0], Ly = box[4], Lz = box[8];
        float iLx = 1.0f / Lx, iLy = 1.0f / Ly, iLz = 1.0f / Lz;
        int il  = tid & (TSIZE - 1);     // i_local 0..127
        int qtr = tid >> 7;              // j-slice 0..7 (16 j each)
        int jbase = qtr * 16;
        float accTot = 0.0f;

        for (int t = gid - NMESH; t < TILES; t += NDIRB) {
            // decode triangle tile t -> (bx, by), by >= bx
            int L = t, bx = 0;
            while (L >= TDIM - bx) { L -= TDIM - bx; bx++; }
            int by = bx + L;

            __syncthreads();             // protect sj reuse across tiles
            if (tid < TSIZE) {
                int jg = by * TSIZE + tid;
                sj[tid] = make_float4(pos[3*jg], pos[3*jg+1], pos[3*jg+2], chg[jg]);
            }
            __syncthreads();

            int i = bx * TSIZE + il;
            float xi = pos[3*i], yi = pos[3*i+1], zi = pos[3*i+2], qi = chg[i];
            float acc = 0.0f;
            if (bx == by) {
                #pragma unroll 8
                for (int jj = 0; jj < 16; jj++) {
                    float4 p = sj[jbase + jj];
                    float dx = xi - p.x; dx -= Lx * rintf(dx * iLx);
                    float dy = yi - p.y; dy -= Ly * rintf(dy * iLy);
                    float dz = zi - p.z; dz -= Lz * rintf(dz * iLz);
                    float r2 = fmaf(dx, dx, fmaf(dy, dy, dz * dz));
                    if (r2 < CUT2 && (jbase + jj) != il) {
                        float rinv = rsqrtf(r2);
                        float x = ALPHAF * r2 * rinv;
                        acc = fmaf(qi * p.w * erfc_fast(x), rinv, acc);
                    }
                }
                accTot += acc;
            } else {
                #pragma unroll 8
                for (int jj = 0; jj < 16; jj++) {
                    float4 p = sj[jbase + jj];
                    float dx = xi - p.x; dx -= Lx * rintf(dx * iLx);
                    float dy = yi - p.y; dy -= Ly * rintf(dy * iLy);
                    float dz = zi - p.z; dz -= Lz * rintf(dz * iLz);
                    float r2 = fmaf(dx, dx, fmaf(dy, dy, dz * dz));
                    if (r2 < CUT2) {
                        float rinv = rsqrtf(r2);
                        float x = ALPHAF * r2 * rinv;
                        acc = fmaf(qi * p.w * erfc_fast(x), rinv, acc);
                    }
                }
                accTot += 2.0f * acc;    // unordered off-diagonal pairs once
            }
        }
        #pragma unroll
        for (int o = 16; o; o >>= 1) accTot += __shfl_xor_sync(0xffffffffu, accTot, o);
        if (lane == 0) sred[wid] = accTot;
        __syncthreads();
        if (tid == 0) {
            float s = 0.0f;
            #pragma unroll
            for (int w = 0; w < 32; w++) s += sred[w];
            atomicAdd(&g_edir, (double)s);
        }
    }

    // ================= arrival counter: last block combines =================
    __syncthreads();
    if (tid == 0) {
        __threadfence();
        unsigned done = atomicAdd(&g_done, 1u);
        if (done == NBLK - 1) {
            __threadfence();             // acquire all blocks' writes
            const double SQRT_PI = 1.7724538509055159;
            double edir  = 0.5 * COULOMB * g_edir;
            double erec  = COULOMB / (2.0 * 3.141592653589793 * g_V) * g_erec;
            double eself = -COULOMB * ALPHAD / SQRT_PI * g_q2;
            out[0] = (float)(edir - (erec + eself));
            // leave-clean for next replay
            g_edir = 0.0; g_erec = 0.0; g_q2 = 0.0;
            __threadfence();
            *(volatile unsigned*)&g_done = 0;
        }
    }
}

extern "C" void kernel_launch(void* const* d_in, const int* in_sizes, int n_in,
                              void* d_out, int out_size) {
    int ip = 0, ic = 1, ib = 2;
    for (int k = 0; k < n_in; k++) {
        if (in_sizes[k] == NATOMS * 3) ip = k;
        else if (in_sizes[k] == NATOMS) ic = k;
        else if (in_sizes[k] == 9)      ib = k;
    }
    const float* pos = (const float*)d_in[ip];
    const float* chg = (const float*)d_in[ic];
    const float* box = (const float*)d_in[ib];
    float* out = (float*)d_out;

    k_all<<<NBLK, NTHR>>>(pos, chg, box, out);
}